// round 14
// baseline (speedup 1.0000x reference)
#include <cuda_runtime.h>
#include <cuda_fp16.h>
#include <cstdint>

// Problem constants
static constexpr int B_  = 8;
static constexpr int L_  = 8192;
static constexpr int S_  = 512;
static constexpr int DQ_ = 256;
static constexpr int DC_ = 768;
static constexpr int H_  = 8;
static constexpr int IN_ = 512;   // H*DH
static constexpr int LOG2L = 13;  // log2(L_)

// ---------------- static device scratch (no allocations allowed) ----------------
__device__ __half g_Wq[DQ_ * IN_];
__device__ __half g_Wkv[DC_ * 1024];          // [DC][ Wk(512) | Wv(512) ]
__device__ __half g_Wo[IN_ * DQ_];
__device__ __half g_q[(size_t)B_ * L_ * IN_];
__device__ __half g_kv[(size_t)B_ * S_ * 1024]; // [B*S][ K(512) | V(512) ]
__device__ __half g_o[(size_t)B_ * L_ * IN_];

// ---------------- small helpers ----------------
__device__ __forceinline__ uint32_t smem_u32(const void* p) {
    return (uint32_t)__cvta_generic_to_shared(p);
}
__device__ __forceinline__ void ldsm_x4(uint32_t* r, const void* p) {
    uint32_t a = smem_u32(p);
    asm volatile("ldmatrix.sync.aligned.m8n8.x4.shared.b16 {%0,%1,%2,%3}, [%4];"
                 : "=r"(r[0]), "=r"(r[1]), "=r"(r[2]), "=r"(r[3]) : "r"(a));
}
__device__ __forceinline__ void ldsm_x4_t(uint32_t* r, const void* p) {
    uint32_t a = smem_u32(p);
    asm volatile("ldmatrix.sync.aligned.m8n8.x4.trans.shared.b16 {%0,%1,%2,%3}, [%4];"
                 : "=r"(r[0]), "=r"(r[1]), "=r"(r[2]), "=r"(r[3]) : "r"(a));
}
__device__ __forceinline__ void ldsm_x4_addr(uint32_t* r, uint32_t a) {
    asm volatile("ldmatrix.sync.aligned.m8n8.x4.shared.b16 {%0,%1,%2,%3}, [%4];"
                 : "=r"(r[0]), "=r"(r[1]), "=r"(r[2]), "=r"(r[3]) : "r"(a));
}
__device__ __forceinline__ void ldsm_x4_t_addr(uint32_t* r, uint32_t a) {
    asm volatile("ldmatrix.sync.aligned.m8n8.x4.trans.shared.b16 {%0,%1,%2,%3}, [%4];"
                 : "=r"(r[0]), "=r"(r[1]), "=r"(r[2]), "=r"(r[3]) : "r"(a));
}
__device__ __forceinline__ void mma16816(float* c, const uint32_t* a, const uint32_t* b) {
    asm volatile(
        "mma.sync.aligned.m16n8k16.row.col.f32.f16.f16.f32 "
        "{%0,%1,%2,%3}, {%4,%5,%6,%7}, {%8,%9}, {%0,%1,%2,%3};"
        : "+f"(c[0]), "+f"(c[1]), "+f"(c[2]), "+f"(c[3])
        : "r"(a[0]), "r"(a[1]), "r"(a[2]), "r"(a[3]), "r"(b[0]), "r"(b[1]));
}
__device__ __forceinline__ uint32_t h2_as_u32(__half2 h) {
    return *reinterpret_cast<uint32_t*>(&h);
}
__device__ __forceinline__ float ex2(float x) {
    float y;
    asm("ex2.approx.ftz.f32 %0, %1;" : "=f"(y) : "f"(x));
    return y;
}
__device__ __forceinline__ void cp_async16(uint32_t dst, const void* src) {
    asm volatile("cp.async.cg.shared.global [%0], [%1], 16;\n" :: "r"(dst), "l"(src));
}
__device__ __forceinline__ void cp_commit() {
    asm volatile("cp.async.commit_group;\n" ::: "memory");
}
__device__ __forceinline__ void cp_wait0() {
    asm volatile("cp.async.wait_group 0;\n" ::: "memory");
}

// ---------------- fused weight conversion (one launch) ----------------
__global__ void f2h_all(const float* __restrict__ Wq, const float* __restrict__ Wk,
                        const float* __restrict__ Wv, const float* __restrict__ Wo,
                        __half* __restrict__ dWq, __half* __restrict__ dWkv,
                        __half* __restrict__ dWo) {
    const int NQ = DQ_ * IN_ / 4;   // 32768 vec4
    const int NK = DC_ * IN_ / 4;   // 98304 vec4
    int i = blockIdx.x * 256 + threadIdx.x;
    float4 v;
    __half* dst;
    if (i < NQ) {
        v = ((const float4*)Wq)[i];
        dst = dWq + i * 4;
    } else if (i < NQ + NK) {
        int j = i - NQ;
        v = ((const float4*)Wk)[j];
        int j4 = j * 4;
        dst = dWkv + (j4 >> 9) * 1024 + (j4 & 511);
    } else if (i < NQ + 2 * NK) {
        int j = i - NQ - NK;
        v = ((const float4*)Wv)[j];
        int j4 = j * 4;
        dst = dWkv + (j4 >> 9) * 1024 + 512 + (j4 & 511);
    } else {
        int j = i - NQ - 2 * NK;
        v = ((const float4*)Wo)[j];
        dst = dWo + j * 4;
    }
    __half2* d2 = (__half2*)dst;
    d2[0] = __floats2half2_rn(v.x, v.y);
    d2[1] = __floats2half2_rn(v.z, v.w);
}

// ---------------- pipelined tiled GEMM (R8 version, unchanged) --------------
template <bool A_F32, bool C_F32, bool GATE_SKIP, bool GATE_ZERO, bool BIAS>
__global__ void __launch_bounds__(256)
gemm_mma(const void* __restrict__ Av, const __half* __restrict__ Bw, void* __restrict__ Cv,
         int M, int N, int K, const int* __restrict__ seq, const float* __restrict__ bias,
         float oscale) {
    const int bn = blockIdx.x, bm = blockIdx.y;
    const int t = threadIdx.x, lane = t & 31, w = t >> 5;
    const int wm = w & 3, wn = w >> 2;

    if (GATE_SKIP) {
        int r0 = bm * 128;
        if ((r0 & (L_ - 1)) >= seq[r0 >> LOG2L]) return;
    }
    int slen_blk = 0;
    if (GATE_ZERO) {
        int r0 = bm * 128;
        slen_blk = seq[r0 >> LOG2L];
        if ((r0 & (L_ - 1)) >= slen_blk) {
            float* Cf = (float*)Cv;
            float4 z = make_float4(0.f, 0.f, 0.f, 0.f);
            for (int i = t; i < 128 * (128 / 4); i += 256) {
                int r = i / (128 / 4), c4 = (i % (128 / 4)) * 4;
                *(float4*)&Cf[(size_t)(bm * 128 + r) * N + bn * 128 + c4] = z;
            }
            return;
        }
    }

    __shared__ __align__(16) __half sA[2][128][40];
    __shared__ __align__(16) __half sB[2][32][136];

    float acc[2][8][4];
#pragma unroll
    for (int mi = 0; mi < 2; mi++)
#pragma unroll
        for (int ni = 0; ni < 8; ni++)
#pragma unroll
            for (int j = 0; j < 4; j++) acc[mi][ni][j] = 0.f;

    const float* A32 = (const float*)Av;
    const __half* A16 = (const __half*)Av;

    const int arow = t >> 3, ac = (t & 7) * 4;
    const int brow = t >> 4, bc = (t & 15) * 8;
    const int li15 = lane & 15;
    const int hi8 = (lane >> 4) << 3;
    const int nk = K / 32;

    float4 af[4];
    uint2 ah[4];

    if (A_F32) {
#pragma unroll
        for (int p = 0; p < 4; p++)
            af[p] = *(const float4*)(A32 + (size_t)(bm * 128 + arow + 32 * p) * K + ac);
    } else {
#pragma unroll
        for (int p = 0; p < 4; p++)
            ah[p] = *(const uint2*)(A16 + (size_t)(bm * 128 + arow + 32 * p) * K + ac);
    }
#pragma unroll
    for (int p = 0; p < 2; p++)
        cp_async16(smem_u32(&sB[0][brow + 16 * p][bc]),
                   Bw + (size_t)(brow + 16 * p) * N + bn * 128 + bc);
    cp_commit();
    if (A_F32) {
#pragma unroll
        for (int p = 0; p < 4; p++) {
            uint2 u;
            u.x = h2_as_u32(__floats2half2_rn(af[p].x, af[p].y));
            u.y = h2_as_u32(__floats2half2_rn(af[p].z, af[p].w));
            *(uint2*)&sA[0][arow + 32 * p][ac] = u;
        }
    } else {
#pragma unroll
        for (int p = 0; p < 4; p++) *(uint2*)&sA[0][arow + 32 * p][ac] = ah[p];
    }
    cp_wait0();
    __syncthreads();

    for (int kt = 0; kt < nk; kt++) {
        const int cur = kt & 1, nxt = cur ^ 1;
        const bool more = (kt + 1 < nk);
        if (more) {
            if (A_F32) {
#pragma unroll
                for (int p = 0; p < 4; p++)
                    af[p] = *(const float4*)(A32 + (size_t)(bm * 128 + arow + 32 * p) * K +
                                             (kt + 1) * 32 + ac);
            } else {
#pragma unroll
                for (int p = 0; p < 4; p++)
                    ah[p] = *(const uint2*)(A16 + (size_t)(bm * 128 + arow + 32 * p) * K +
                                            (kt + 1) * 32 + ac);
            }
#pragma unroll
            for (int p = 0; p < 2; p++)
                cp_async16(smem_u32(&sB[nxt][brow + 16 * p][bc]),
                           Bw + (size_t)((kt + 1) * 32 + brow + 16 * p) * N + bn * 128 + bc);
            cp_commit();
        }

#pragma unroll
        for (int kk = 0; kk < 2; kk++) {
            uint32_t a[2][4];
#pragma unroll
            for (int mi = 0; mi < 2; mi++)
                ldsm_x4(a[mi], &sA[cur][wm * 32 + mi * 16 + li15][kk * 16 + hi8]);
#pragma unroll
            for (int p = 0; p < 4; p++) {
                uint32_t bb[4];
                ldsm_x4_t(bb, &sB[cur][kk * 16 + li15][wn * 64 + p * 16 + hi8]);
                mma16816(acc[0][2 * p], a[0], bb);
                mma16816(acc[0][2 * p + 1], a[0], bb + 2);
                mma16816(acc[1][2 * p], a[1], bb);
                mma16816(acc[1][2 * p + 1], a[1], bb + 2);
            }
        }

        if (more) {
            if (A_F32) {
#pragma unroll
                for (int p = 0; p < 4; p++) {
                    uint2 u;
                    u.x = h2_as_u32(__floats2half2_rn(af[p].x, af[p].y));
                    u.y = h2_as_u32(__floats2half2_rn(af[p].z, af[p].w));
                    *(uint2*)&sA[nxt][arow + 32 * p][ac] = u;
                }
            } else {
#pragma unroll
                for (int p = 0; p < 4; p++) *(uint2*)&sA[nxt][arow + 32 * p][ac] = ah[p];
            }
            cp_wait0();
            __syncthreads();
        }
    }

    const int row_base = bm * 128 + wm * 32;
    const int col_base = bn * 128 + wn * 64;
    if (C_F32) {
        float* Cf = (float*)Cv;
#pragma unroll
        for (int mi = 0; mi < 2; mi++) {
#pragma unroll
            for (int ni = 0; ni < 8; ni++) {
                int r = row_base + mi * 16 + (lane >> 2);
                int c = col_base + ni * 8 + (lane & 3) * 2;
                float b0 = BIAS ? bias[c] : 0.f;
                float b1 = BIAS ? bias[c + 1] : 0.f;
                bool v0 = !GATE_ZERO || ((r & (L_ - 1)) < slen_blk);
                bool v1 = !GATE_ZERO || (((r + 8) & (L_ - 1)) < slen_blk);
                float2 o0 = v0 ? make_float2(acc[mi][ni][0] + b0, acc[mi][ni][1] + b1)
                               : make_float2(0.f, 0.f);
                float2 o1 = v1 ? make_float2(acc[mi][ni][2] + b0, acc[mi][ni][3] + b1)
                               : make_float2(0.f, 0.f);
                *(float2*)&Cf[(size_t)r * N + c] = o0;
                *(float2*)&Cf[(size_t)(r + 8) * N + c] = o1;
            }
        }
    } else {
        __half* Ch = (__half*)Cv;
#pragma unroll
        for (int mi = 0; mi < 2; mi++) {
#pragma unroll
            for (int ni = 0; ni < 8; ni++) {
                int r = row_base + mi * 16 + (lane >> 2);
                int c = col_base + ni * 8 + (lane & 3) * 2;
                *(__half2*)(Ch + (size_t)r * N + c) =
                    __floats2half2_rn(acc[mi][ni][0] * oscale, acc[mi][ni][1] * oscale);
                *(__half2*)(Ch + (size_t)(r + 8) * N + c) =
                    __floats2half2_rn(acc[mi][ni][2] * oscale, acc[mi][ni][3] * oscale);
            }
        }
    }
}

// ---------------- persistent-KV flash attention (barrier-free main loop) ----
// grid (8, H, B), 384 threads / 12 warps, 1 CTA per SM (128 KB smem).
// Each CTA loads its (b,h) K[512x64] and V[512x64] ONCE into smem (SW128
// swizzle on packed 128B rows), then warps independently sweep 32-row Q tiles
// (Q fragments loaded directly from gmem). No __syncthreads / cp.waits in the
// steady state. R8's proven inner pipeline: 2-group rotating score buffer,
// f32 max-free softmax in log2 domain (Q pre-scaled by 0.125*log2e).
static constexpr int ATTN_SMEM = 2 * S_ * 64 * 2;   // 131072 bytes
static constexpr int QSPLIT = 8;                    // q-rows per CTA = L/8 = 1024

// score group g: QK MMAs for S rows 16g..16g+15 into sacc[B]
#define QK_G(gv, Bb) do {                                                       \
    _Pragma("unroll") for (int mi_ = 0; mi_ < 2; mi_++)                          \
    _Pragma("unroll") for (int ns_ = 0; ns_ < 2; ns_++)                          \
    _Pragma("unroll") for (int j_ = 0; j_ < 4; j_++) sacc[Bb][mi_][ns_][j_] = 0.f; \
    uint32_t kb_ = kaddr + (uint32_t)(gv) * 2048u;                               \
    _Pragma("unroll") for (int ks_ = 0; ks_ < 4; ks_++) {                        \
        uint32_t bb_[4];                                                         \
        ldsm_x4_addr(bb_, kb_ + kc[ks_]);                                        \
        mma16816(sacc[Bb][0][0], aq[0][ks_], bb_);                               \
        mma16816(sacc[Bb][0][1], aq[0][ks_], bb_ + 2);                           \
        mma16816(sacc[Bb][1][0], aq[1][ks_], bb_);                               \
        mma16816(sacc[Bb][1][1], aq[1][ks_], bb_ + 2);                           \
    }                                                                            \
} while (0)

// softmax (f32 ex2, max-free) + PV MMAs for group g from sacc[B]
#define SMPV_G(gv, Bb) do {                                                     \
    uint32_t pp_[2][4];                                                          \
    _Pragma("unroll") for (int mi_ = 0; mi_ < 2; mi_++) {                        \
        float p0 = ex2(sacc[Bb][mi_][0][0]), p1 = ex2(sacc[Bb][mi_][0][1]);      \
        float p2 = ex2(sacc[Bb][mi_][0][2]), p3 = ex2(sacc[Bb][mi_][0][3]);      \
        float p4 = ex2(sacc[Bb][mi_][1][0]), p5 = ex2(sacc[Bb][mi_][1][1]);      \
        float p6 = ex2(sacc[Bb][mi_][1][2]), p7 = ex2(sacc[Bb][mi_][1][3]);      \
        lsp[mi_][0] += (p0 + p1) + (p4 + p5);                                    \
        lsp[mi_][1] += (p2 + p3) + (p6 + p7);                                    \
        pp_[mi_][0] = h2_as_u32(__floats2half2_rn(p0, p1));                      \
        pp_[mi_][1] = h2_as_u32(__floats2half2_rn(p2, p3));                      \
        pp_[mi_][2] = h2_as_u32(__floats2half2_rn(p4, p5));                      \
        pp_[mi_][3] = h2_as_u32(__floats2half2_rn(p6, p7));                      \
    }                                                                            \
    uint32_t vb_ = vaddr + (uint32_t)(gv) * 2048u;                               \
    _Pragma("unroll") for (int p_ = 0; p_ < 4; p_++) {                           \
        uint32_t bv_[4];                                                         \
        ldsm_x4_t_addr(bv_, vb_ + vc[p_]);                                       \
        mma16816(oa[0][2 * p_], pp_[0], bv_);                                    \
        mma16816(oa[0][2 * p_ + 1], pp_[0], bv_ + 2);                            \
        mma16816(oa[1][2 * p_], pp_[1], bv_);                                    \
        mma16816(oa[1][2 * p_ + 1], pp_[1], bv_ + 2);                            \
    }                                                                            \
} while (0)

__global__ void __launch_bounds__(384, 1)
attn_kernel(const int* __restrict__ seq) {
    const int sp = blockIdx.x, h = blockIdx.y, b = blockIdx.z;
    const int slen = seq[b];
    const int q0 = sp * (L_ / QSPLIT);
    if (q0 >= slen) return;

    extern __shared__ __align__(16) __half sme[];
    const uint32_t smem0 = smem_u32(sme);

    const int t = threadIdx.x, lane = t & 31, w = t >> 5;   // w in 0..11
    const int li15 = lane & 15, li7 = lane & 7, c8 = lane & 8;
    const int hi1 = lane >> 4, hi8 = hi1 << 3;

    // ---- load K and V for (b,h) into smem, SW128-swizzled 128B rows ----
    {
        const __half* base = g_kv + (size_t)b * S_ * 1024 + h * 64;
        for (int i = t; i < 8192; i += 384) {
            int region = i >> 12;          // 0 = K, 1 = V
            int idx = i & 4095;
            int row = idx >> 3, seg = idx & 7;
            uint32_t off = (uint32_t)row * 128 + seg * 16;
            uint32_t sw = off ^ ((off >> 3) & 0x70);
            cp_async16(smem0 + region * 65536 + sw,
                       base + (size_t)row * 1024 + region * 512 + seg * 8);
        }
        cp_commit();
        cp_wait0();
    }
    __syncthreads();   // the ONLY barrier

    // per-lane ldmatrix address precomputation (swizzle constant per lane)
    const int krb = hi1 * 8 + li7;                      // K row-in-group
    const uint32_t kaddr = smem0 + (uint32_t)krb * 128;
    uint32_t kc[4];
#pragma unroll
    for (int ks = 0; ks < 4; ks++)
        kc[ks] = (uint32_t)((ks * 32 + c8 * 2) ^ ((krb & 7) << 4));

    const uint32_t vaddr = smem0 + 65536u + (uint32_t)li15 * 128;
    uint32_t vc[4];
#pragma unroll
    for (int p = 0; p < 4; p++)
        vc[p] = (uint32_t)((p * 32 + hi8 * 2) ^ ((li15 & 7) << 4));

    // ---- independent per-warp sweep over 32-row Q tiles ----
    for (int tile = w; tile < (L_ / QSPLIT) / 32; tile += 12) {
        const int qrow = q0 + tile * 32;
        if (qrow >= slen) continue;

        // Q fragments straight from gmem (pre-scaled into log2 domain)
        uint32_t aq[2][4][4];
#pragma unroll
        for (int mi = 0; mi < 2; mi++)
#pragma unroll
            for (int ks = 0; ks < 4; ks++) {
                const __half* qp = g_q + ((size_t)b * L_ + qrow + mi * 16 + (lane >> 2)) * IN_ +
                                   h * 64 + ks * 16 + (lane & 3) * 2;
                aq[mi][ks][0] = *(const uint32_t*)qp;
                aq[mi][ks][1] = *(const uint32_t*)(qp + 8 * IN_);
                aq[mi][ks][2] = *(const uint32_t*)(qp + 8);
                aq[mi][ks][3] = *(const uint32_t*)(qp + 8 * IN_ + 8);
            }

        float lsp[2][2];
        lsp[0][0] = lsp[0][1] = lsp[1][0] = lsp[1][1] = 0.f;
        float oa[2][8][4];
#pragma unroll
        for (int mi = 0; mi < 2; mi++)
#pragma unroll
            for (int nd = 0; nd < 8; nd++)
#pragma unroll
                for (int j = 0; j < 4; j++) oa[mi][nd][j] = 0.f;

        float sacc[2][2][2][4];

        // software pipeline over 32 groups of 16 S-rows (2 groups per iter)
        QK_G(0, 0);
        for (int g = 0; g < 30; g += 2) {
            QK_G(g + 1, 1);
            SMPV_G(g, 0);
            QK_G(g + 2, 0);
            SMPV_G(g + 1, 1);
        }
        QK_G(31, 1);
        SMPV_G(30, 0);
        SMPV_G(31, 1);

        // epilogue: row-sum reduction, normalize, store fp16
#pragma unroll
        for (int mi = 0; mi < 2; mi++) {
            float s0 = lsp[mi][0], s1 = lsp[mi][1];
            s0 += __shfl_xor_sync(0xffffffffu, s0, 1);
            s0 += __shfl_xor_sync(0xffffffffu, s0, 2);
            s1 += __shfl_xor_sync(0xffffffffu, s1, 1);
            s1 += __shfl_xor_sync(0xffffffffu, s1, 2);
            float inv0 = __fdividef(1.f, s0);
            float inv1 = __fdividef(1.f, s1);
            int r = qrow + mi * 16 + (lane >> 2);
            size_t base0 = ((size_t)b * L_ + r) * IN_ + h * 64 + (lane & 3) * 2;
            size_t base1 = base0 + (size_t)8 * IN_;
#pragma unroll
            for (int nd = 0; nd < 8; nd++) {
                *(__half2*)(g_o + base0 + nd * 8) =
                    __floats2half2_rn(oa[mi][nd][0] * inv0, oa[mi][nd][1] * inv0);
                *(__half2*)(g_o + base1 + nd * 8) =
                    __floats2half2_rn(oa[mi][nd][2] * inv1, oa[mi][nd][3] * inv1);
            }
        }
    }
}

// ---------------- launch ----------------
extern "C" void kernel_launch(void* const* d_in, const int* in_sizes, int n_in,
                              void* d_out, int out_size) {
    const float* x   = (const float*)d_in[0];
    const float* ctx = (const float*)d_in[1];
    const int*   seq = (const int*)d_in[2];
    const float* Wq  = (const float*)d_in[3];
    const float* Wk  = (const float*)d_in[4];
    const float* Wv  = (const float*)d_in[5];
    const float* Wo  = (const float*)d_in[6];
    const float* bo  = (const float*)d_in[7];
    float* out = (float*)d_out;

    void *pWq, *pWkv, *pWo, *pQ, *pKV, *pO;
    cudaGetSymbolAddress(&pWq, g_Wq);
    cudaGetSymbolAddress(&pWkv, g_Wkv);
    cudaGetSymbolAddress(&pWo, g_Wo);
    cudaGetSymbolAddress(&pQ, g_q);
    cudaGetSymbolAddress(&pKV, g_kv);
    cudaGetSymbolAddress(&pO, g_o);

    const float kQScale = 0.125f * 1.44269504088896f;  // 1/sqrt(DH) * log2(e)

    cudaFuncSetAttribute(attn_kernel, cudaFuncAttributeMaxDynamicSharedMemorySize,
                         ATTN_SMEM);

    // 1. convert all weights in one launch
    f2h_all<<<1024, 256>>>(Wq, Wk, Wv, Wo, (__half*)pWq, (__half*)pWkv, (__half*)pWo);

    // 2. fused K+V projection: [B*S, DC] @ [DC, 1024] -> g_kv
    gemm_mma<true, false, false, false, false>
        <<<dim3(1024 / 128, (B_ * S_) / 128), 256>>>(ctx, (const __half*)pWkv, pKV,
                                                     B_ * S_, 1024, DC_, nullptr, nullptr, 1.0f);

    // 3. Q projection, output pre-scaled into log2 softmax domain
    gemm_mma<true, false, true, false, false>
        <<<dim3(IN_ / 128, (B_ * L_) / 128), 256>>>(x, (const __half*)pWq, pQ,
                                                    B_ * L_, IN_, DQ_, seq, nullptr, kQScale);

    // 4. persistent-KV attention (barrier-free main loop)
    attn_kernel<<<dim3(QSPLIT, H_, B_), 384, ATTN_SMEM>>>(seq);

    // 5. output projection + bias + seq_len zero-gating
    gemm_mma<false, true, false, true, true>
        <<<dim3(DQ_ / 128, (B_ * L_) / 128), 256>>>(pO, (const __half*)pWo, out,
                                                    B_ * L_, DQ_, IN_, seq, bo, 1.0f);
}

// round 15
// speedup vs baseline: 1.1240x; 1.1240x over previous
#include <cuda_runtime.h>
#include <cuda_fp16.h>
#include <cstdint>

// Problem constants
static constexpr int B_  = 8;
static constexpr int L_  = 8192;
static constexpr int S_  = 512;
static constexpr int DQ_ = 256;
static constexpr int DC_ = 768;
static constexpr int H_  = 8;
static constexpr int IN_ = 512;   // H*DH
static constexpr int LOG2L = 13;  // log2(L_)

// ---------------- static device scratch (no allocations allowed) ----------------
__device__ __half g_Wq[DQ_ * IN_];
__device__ __half g_Wkv[DC_ * 1024];          // [DC][ Wk(512) | Wv(512) ]
__device__ __half g_Wo[IN_ * DQ_];
__device__ __half g_q[(size_t)B_ * L_ * IN_];
__device__ __half g_kv[(size_t)B_ * S_ * 1024]; // [B*S][ K(512) | V(512) ]
__device__ __half g_o[(size_t)B_ * L_ * IN_];

// ---------------- small helpers ----------------
__device__ __forceinline__ uint32_t smem_u32(const void* p) {
    return (uint32_t)__cvta_generic_to_shared(p);
}
__device__ __forceinline__ void ldsm_x4(uint32_t* r, const void* p) {
    uint32_t a = smem_u32(p);
    asm volatile("ldmatrix.sync.aligned.m8n8.x4.shared.b16 {%0,%1,%2,%3}, [%4];"
                 : "=r"(r[0]), "=r"(r[1]), "=r"(r[2]), "=r"(r[3]) : "r"(a));
}
__device__ __forceinline__ void ldsm_x4_t(uint32_t* r, const void* p) {
    uint32_t a = smem_u32(p);
    asm volatile("ldmatrix.sync.aligned.m8n8.x4.trans.shared.b16 {%0,%1,%2,%3}, [%4];"
                 : "=r"(r[0]), "=r"(r[1]), "=r"(r[2]), "=r"(r[3]) : "r"(a));
}
__device__ __forceinline__ void mma16816(float* c, const uint32_t* a, const uint32_t* b) {
    asm volatile(
        "mma.sync.aligned.m16n8k16.row.col.f32.f16.f16.f32 "
        "{%0,%1,%2,%3}, {%4,%5,%6,%7}, {%8,%9}, {%0,%1,%2,%3};"
        : "+f"(c[0]), "+f"(c[1]), "+f"(c[2]), "+f"(c[3])
        : "r"(a[0]), "r"(a[1]), "r"(a[2]), "r"(a[3]), "r"(b[0]), "r"(b[1]));
}
__device__ __forceinline__ uint32_t h2_as_u32(__half2 h) {
    return *reinterpret_cast<uint32_t*>(&h);
}
__device__ __forceinline__ float ex2(float x) {
    float y;
    asm("ex2.approx.ftz.f32 %0, %1;" : "=f"(y) : "f"(x));
    return y;
}
__device__ __forceinline__ void cp_async16(uint32_t dst, const void* src) {
    asm volatile("cp.async.cg.shared.global [%0], [%1], 16;\n" :: "r"(dst), "l"(src));
}
__device__ __forceinline__ void cp_commit() {
    asm volatile("cp.async.commit_group;\n" ::: "memory");
}
__device__ __forceinline__ void cp_wait0() {
    asm volatile("cp.async.wait_group 0;\n" ::: "memory");
}

// ---------------- fused weight conversion (one launch) ----------------
__global__ void f2h_all(const float* __restrict__ Wq, const float* __restrict__ Wk,
                        const float* __restrict__ Wv, const float* __restrict__ Wo,
                        __half* __restrict__ dWq, __half* __restrict__ dWkv,
                        __half* __restrict__ dWo) {
    const int NQ = DQ_ * IN_ / 4;   // 32768 vec4
    const int NK = DC_ * IN_ / 4;   // 98304 vec4
    int i = blockIdx.x * 256 + threadIdx.x;
    float4 v;
    __half* dst;
    if (i < NQ) {
        v = ((const float4*)Wq)[i];
        dst = dWq + i * 4;
    } else if (i < NQ + NK) {
        int j = i - NQ;
        v = ((const float4*)Wk)[j];
        int j4 = j * 4;
        dst = dWkv + (j4 >> 9) * 1024 + (j4 & 511);
    } else if (i < NQ + 2 * NK) {
        int j = i - NQ - NK;
        v = ((const float4*)Wv)[j];
        int j4 = j * 4;
        dst = dWkv + (j4 >> 9) * 1024 + 512 + (j4 & 511);
    } else {
        int j = i - NQ - 2 * NK;
        v = ((const float4*)Wo)[j];
        dst = dWo + j * 4;
    }
    __half2* d2 = (__half2*)dst;
    d2[0] = __floats2half2_rn(v.x, v.y);
    d2[1] = __floats2half2_rn(v.z, v.w);
}

// ---------------- fused KV-proj + Q-proj in ONE launch -----------------------
// CTAs [0, 256):   C_kv[4096,1024] = ctx[4096,768] @ Wkv            (no gate)
// CTAs [256, 2304): C_q[65536,512] = x[65536,256] @ Wq  (seq-gated, *qscale)
// Body = R8 pipelined f32-A GEMM with runtime dims; per-CTA-uniform branches.
__global__ void __launch_bounds__(256)
gemm_qkv(const float* __restrict__ ctx, const __half* __restrict__ Wkv, __half* __restrict__ Ckv,
         const float* __restrict__ x, const __half* __restrict__ Wq, __half* __restrict__ Cq,
         const int* __restrict__ seq, float qscale) {
    const int bid = blockIdx.x;
    const float* A32;
    const __half* Bw;
    __half* Cv;
    int bn, bm, N, K;
    float oscale;
    if (bid < 256) {
        A32 = ctx; Bw = Wkv; Cv = Ckv;
        bn = bid & 7; bm = bid >> 3;
        N = 1024; K = DC_; oscale = 1.0f;
    } else {
        const int j = bid - 256;
        A32 = x; Bw = Wq; Cv = Cq;
        bn = j & 3; bm = j >> 2;
        N = IN_; K = DQ_; oscale = qscale;
        int r0 = bm * 128;
        if ((r0 & (L_ - 1)) >= seq[r0 >> LOG2L]) return;
    }

    const int t = threadIdx.x, lane = t & 31, w = t >> 5;
    const int wm = w & 3, wn = w >> 2;

    __shared__ __align__(16) __half sA[2][128][40];
    __shared__ __align__(16) __half sB[2][32][136];

    float acc[2][8][4];
#pragma unroll
    for (int mi = 0; mi < 2; mi++)
#pragma unroll
        for (int ni = 0; ni < 8; ni++)
#pragma unroll
            for (int j = 0; j < 4; j++) acc[mi][ni][j] = 0.f;

    const int arow = t >> 3, ac = (t & 7) * 4;
    const int brow = t >> 4, bc = (t & 15) * 8;
    const int li15 = lane & 15;
    const int hi8 = (lane >> 4) << 3;
    const int nk = K / 32;

    float4 af[4];

#pragma unroll
    for (int p = 0; p < 4; p++)
        af[p] = *(const float4*)(A32 + (size_t)(bm * 128 + arow + 32 * p) * K + ac);
#pragma unroll
    for (int p = 0; p < 2; p++)
        cp_async16(smem_u32(&sB[0][brow + 16 * p][bc]),
                   Bw + (size_t)(brow + 16 * p) * N + bn * 128 + bc);
    cp_commit();
#pragma unroll
    for (int p = 0; p < 4; p++) {
        uint2 u;
        u.x = h2_as_u32(__floats2half2_rn(af[p].x, af[p].y));
        u.y = h2_as_u32(__floats2half2_rn(af[p].z, af[p].w));
        *(uint2*)&sA[0][arow + 32 * p][ac] = u;
    }
    cp_wait0();
    __syncthreads();

    for (int kt = 0; kt < nk; kt++) {
        const int cur = kt & 1, nxt = cur ^ 1;
        const bool more = (kt + 1 < nk);
        if (more) {
#pragma unroll
            for (int p = 0; p < 4; p++)
                af[p] = *(const float4*)(A32 + (size_t)(bm * 128 + arow + 32 * p) * K +
                                         (kt + 1) * 32 + ac);
#pragma unroll
            for (int p = 0; p < 2; p++)
                cp_async16(smem_u32(&sB[nxt][brow + 16 * p][bc]),
                           Bw + (size_t)((kt + 1) * 32 + brow + 16 * p) * N + bn * 128 + bc);
            cp_commit();
        }

#pragma unroll
        for (int kk = 0; kk < 2; kk++) {
            uint32_t a[2][4];
#pragma unroll
            for (int mi = 0; mi < 2; mi++)
                ldsm_x4(a[mi], &sA[cur][wm * 32 + mi * 16 + li15][kk * 16 + hi8]);
#pragma unroll
            for (int p = 0; p < 4; p++) {
                uint32_t bb[4];
                ldsm_x4_t(bb, &sB[cur][kk * 16 + li15][wn * 64 + p * 16 + hi8]);
                mma16816(acc[0][2 * p], a[0], bb);
                mma16816(acc[0][2 * p + 1], a[0], bb + 2);
                mma16816(acc[1][2 * p], a[1], bb);
                mma16816(acc[1][2 * p + 1], a[1], bb + 2);
            }
        }

        if (more) {
#pragma unroll
            for (int p = 0; p < 4; p++) {
                uint2 u;
                u.x = h2_as_u32(__floats2half2_rn(af[p].x, af[p].y));
                u.y = h2_as_u32(__floats2half2_rn(af[p].z, af[p].w));
                *(uint2*)&sA[nxt][arow + 32 * p][ac] = u;
            }
            cp_wait0();
            __syncthreads();
        }
    }

    const int row_base = bm * 128 + wm * 32;
    const int col_base = bn * 128 + wn * 64;
#pragma unroll
    for (int mi = 0; mi < 2; mi++) {
#pragma unroll
        for (int ni = 0; ni < 8; ni++) {
            int r = row_base + mi * 16 + (lane >> 2);
            int c = col_base + ni * 8 + (lane & 3) * 2;
            *(__half2*)(Cv + (size_t)r * N + c) =
                __floats2half2_rn(acc[mi][ni][0] * oscale, acc[mi][ni][1] * oscale);
            *(__half2*)(Cv + (size_t)(r + 8) * N + c) =
                __floats2half2_rn(acc[mi][ni][2] * oscale, acc[mi][ni][3] * oscale);
        }
    }
}

// ---------------- pipelined tiled GEMM (R8 template, used for O-proj) -------
template <bool A_F32, bool C_F32, bool GATE_SKIP, bool GATE_ZERO, bool BIAS>
__global__ void __launch_bounds__(256)
gemm_mma(const void* __restrict__ Av, const __half* __restrict__ Bw, void* __restrict__ Cv,
         int M, int N, int K, const int* __restrict__ seq, const float* __restrict__ bias,
         float oscale) {
    const int bn = blockIdx.x, bm = blockIdx.y;
    const int t = threadIdx.x, lane = t & 31, w = t >> 5;
    const int wm = w & 3, wn = w >> 2;

    if (GATE_SKIP) {
        int r0 = bm * 128;
        if ((r0 & (L_ - 1)) >= seq[r0 >> LOG2L]) return;
    }
    int slen_blk = 0;
    if (GATE_ZERO) {
        int r0 = bm * 128;
        slen_blk = seq[r0 >> LOG2L];
        if ((r0 & (L_ - 1)) >= slen_blk) {
            float* Cf = (float*)Cv;
            float4 z = make_float4(0.f, 0.f, 0.f, 0.f);
            for (int i = t; i < 128 * (128 / 4); i += 256) {
                int r = i / (128 / 4), c4 = (i % (128 / 4)) * 4;
                *(float4*)&Cf[(size_t)(bm * 128 + r) * N + bn * 128 + c4] = z;
            }
            return;
        }
    }

    __shared__ __align__(16) __half sA[2][128][40];
    __shared__ __align__(16) __half sB[2][32][136];

    float acc[2][8][4];
#pragma unroll
    for (int mi = 0; mi < 2; mi++)
#pragma unroll
        for (int ni = 0; ni < 8; ni++)
#pragma unroll
            for (int j = 0; j < 4; j++) acc[mi][ni][j] = 0.f;

    const float* A32 = (const float*)Av;
    const __half* A16 = (const __half*)Av;

    const int arow = t >> 3, ac = (t & 7) * 4;
    const int brow = t >> 4, bc = (t & 15) * 8;
    const int li15 = lane & 15;
    const int hi8 = (lane >> 4) << 3;
    const int nk = K / 32;

    float4 af[4];
    uint2 ah[4];

    if (A_F32) {
#pragma unroll
        for (int p = 0; p < 4; p++)
            af[p] = *(const float4*)(A32 + (size_t)(bm * 128 + arow + 32 * p) * K + ac);
    } else {
#pragma unroll
        for (int p = 0; p < 4; p++)
            ah[p] = *(const uint2*)(A16 + (size_t)(bm * 128 + arow + 32 * p) * K + ac);
    }
#pragma unroll
    for (int p = 0; p < 2; p++)
        cp_async16(smem_u32(&sB[0][brow + 16 * p][bc]),
                   Bw + (size_t)(brow + 16 * p) * N + bn * 128 + bc);
    cp_commit();
    if (A_F32) {
#pragma unroll
        for (int p = 0; p < 4; p++) {
            uint2 u;
            u.x = h2_as_u32(__floats2half2_rn(af[p].x, af[p].y));
            u.y = h2_as_u32(__floats2half2_rn(af[p].z, af[p].w));
            *(uint2*)&sA[0][arow + 32 * p][ac] = u;
        }
    } else {
#pragma unroll
        for (int p = 0; p < 4; p++) *(uint2*)&sA[0][arow + 32 * p][ac] = ah[p];
    }
    cp_wait0();
    __syncthreads();

    for (int kt = 0; kt < nk; kt++) {
        const int cur = kt & 1, nxt = cur ^ 1;
        const bool more = (kt + 1 < nk);
        if (more) {
            if (A_F32) {
#pragma unroll
                for (int p = 0; p < 4; p++)
                    af[p] = *(const float4*)(A32 + (size_t)(bm * 128 + arow + 32 * p) * K +
                                             (kt + 1) * 32 + ac);
            } else {
#pragma unroll
                for (int p = 0; p < 4; p++)
                    ah[p] = *(const uint2*)(A16 + (size_t)(bm * 128 + arow + 32 * p) * K +
                                            (kt + 1) * 32 + ac);
            }
#pragma unroll
            for (int p = 0; p < 2; p++)
                cp_async16(smem_u32(&sB[nxt][brow + 16 * p][bc]),
                           Bw + (size_t)((kt + 1) * 32 + brow + 16 * p) * N + bn * 128 + bc);
            cp_commit();
        }

#pragma unroll
        for (int kk = 0; kk < 2; kk++) {
            uint32_t a[2][4];
#pragma unroll
            for (int mi = 0; mi < 2; mi++)
                ldsm_x4(a[mi], &sA[cur][wm * 32 + mi * 16 + li15][kk * 16 + hi8]);
#pragma unroll
            for (int p = 0; p < 4; p++) {
                uint32_t bb[4];
                ldsm_x4_t(bb, &sB[cur][kk * 16 + li15][wn * 64 + p * 16 + hi8]);
                mma16816(acc[0][2 * p], a[0], bb);
                mma16816(acc[0][2 * p + 1], a[0], bb + 2);
                mma16816(acc[1][2 * p], a[1], bb);
                mma16816(acc[1][2 * p + 1], a[1], bb + 2);
            }
        }

        if (more) {
            if (A_F32) {
#pragma unroll
                for (int p = 0; p < 4; p++) {
                    uint2 u;
                    u.x = h2_as_u32(__floats2half2_rn(af[p].x, af[p].y));
                    u.y = h2_as_u32(__floats2half2_rn(af[p].z, af[p].w));
                    *(uint2*)&sA[nxt][arow + 32 * p][ac] = u;
                }
            } else {
#pragma unroll
                for (int p = 0; p < 4; p++) *(uint2*)&sA[nxt][arow + 32 * p][ac] = ah[p];
            }
            cp_wait0();
            __syncthreads();
        }
    }

    const int row_base = bm * 128 + wm * 32;
    const int col_base = bn * 128 + wn * 64;
    if (C_F32) {
        float* Cf = (float*)Cv;
#pragma unroll
        for (int mi = 0; mi < 2; mi++) {
#pragma unroll
            for (int ni = 0; ni < 8; ni++) {
                int r = row_base + mi * 16 + (lane >> 2);
                int c = col_base + ni * 8 + (lane & 3) * 2;
                float b0 = BIAS ? bias[c] : 0.f;
                float b1 = BIAS ? bias[c + 1] : 0.f;
                bool v0 = !GATE_ZERO || ((r & (L_ - 1)) < slen_blk);
                bool v1 = !GATE_ZERO || (((r + 8) & (L_ - 1)) < slen_blk);
                float2 o0 = v0 ? make_float2(acc[mi][ni][0] + b0, acc[mi][ni][1] + b1)
                               : make_float2(0.f, 0.f);
                float2 o1 = v1 ? make_float2(acc[mi][ni][2] + b0, acc[mi][ni][3] + b1)
                               : make_float2(0.f, 0.f);
                *(float2*)&Cf[(size_t)r * N + c] = o0;
                *(float2*)&Cf[(size_t)(r + 8) * N + c] = o1;
            }
        }
    } else {
        __half* Ch = (__half*)Cv;
#pragma unroll
        for (int mi = 0; mi < 2; mi++) {
#pragma unroll
            for (int ni = 0; ni < 8; ni++) {
                int r = row_base + mi * 16 + (lane >> 2);
                int c = col_base + ni * 8 + (lane & 3) * 2;
                *(__half2*)(Ch + (size_t)r * N + c) =
                    __floats2half2_rn(acc[mi][ni][0] * oscale, acc[mi][ni][1] * oscale);
                *(__half2*)(Ch + (size_t)(r + 8) * N + c) =
                    __floats2half2_rn(acc[mi][ni][2] * oscale, acc[mi][ni][3] * oscale);
            }
        }
    }
}

// ---------------- fused flash attention (R8 exact) --------------------------
__global__ void __launch_bounds__(128, 3)
attn_kernel(const int* __restrict__ seq) {
    const int b = blockIdx.z, h = blockIdx.y;
    const int l0 = blockIdx.x * 128;
    if (l0 >= seq[b]) return;

    __shared__ __align__(16) __half sBuf0[2][64][72];
    __shared__ __align__(16) __half sBuf1[2][64][72];

    const int t = threadIdx.x, lane = t & 31, w = t >> 5;
    const int li15 = lane & 15;
    const int li7 = lane & 7;
    const int c8 = lane & 8;
    const int hi1 = lane >> 4;
    const int hi8 = hi1 << 3;

    const int kvr = t >> 1;
    const int kvs = t & 1;
    const size_t kv_row0 = (size_t)b * S_ * 1024 + (size_t)kvr * 1024 + h * 64;

    {
#pragma unroll
        for (int p = 0; p < 4; p++) {
            int seg = kvs + 2 * p;
            cp_async16(smem_u32(&sBuf0[0][kvr][seg * 8]), g_kv + kv_row0 + seg * 8);
            cp_async16(smem_u32(&sBuf0[1][kvr][seg * 8]), g_kv + kv_row0 + 512 + seg * 8);
        }
        cp_commit();
    }

    __half(*sQ)[72] = reinterpret_cast<__half(*)[72]>(sBuf1);
    {
        int row = t >> 3, qc = (t & 7) * 8;
#pragma unroll
        for (int p = 0; p < 8; p++) {
            *(uint4*)&sQ[row + 16 * p][qc] =
                *(const uint4*)(g_q + ((size_t)b * L_ + l0 + row + 16 * p) * IN_ + h * 64 + qc);
        }
    }
    cp_wait0();
    __syncthreads();

    uint32_t aq[2][4][4];
#pragma unroll
    for (int mi = 0; mi < 2; mi++)
#pragma unroll
        for (int ks = 0; ks < 4; ks++)
            ldsm_x4(aq[mi][ks], &sQ[w * 32 + mi * 16 + li15][ks * 16 + hi8]);
    __syncthreads();

    float lsp[2][2];
    lsp[0][0] = lsp[0][1] = lsp[1][0] = lsp[1][1] = 0.f;
    float oa[2][8][4];
#pragma unroll
    for (int mi = 0; mi < 2; mi++)
#pragma unroll
        for (int nd = 0; nd < 8; nd++)
#pragma unroll
            for (int j = 0; j < 4; j++) oa[mi][nd][j] = 0.f;

    for (int sc = 0; sc < 8; sc++) {
        const int cur = sc & 1;
        if (sc < 7) {
            __half(*dst)[64][72] = (cur ? sBuf0 : sBuf1);
            size_t rowb = kv_row0 + (size_t)(sc + 1) * 64 * 1024;
#pragma unroll
            for (int p = 0; p < 4; p++) {
                int seg = kvs + 2 * p;
                cp_async16(smem_u32(&dst[0][kvr][seg * 8]), g_kv + rowb + seg * 8);
                cp_async16(smem_u32(&dst[1][kvr][seg * 8]), g_kv + rowb + 512 + seg * 8);
            }
            cp_commit();
        }

        const __half(*sK)[72] = (cur ? sBuf1[0] : sBuf0[0]);
        const __half(*sV)[72] = (cur ? sBuf1[1] : sBuf0[1]);

        float sacc[2][2][2][4];
#pragma unroll
        for (int g = 0; g < 5; g++) {
            if (g < 4) {
                const int buf = g & 1;
#pragma unroll
                for (int mi = 0; mi < 2; mi++)
#pragma unroll
                    for (int ns = 0; ns < 2; ns++)
#pragma unroll
                        for (int j = 0; j < 4; j++) sacc[buf][mi][ns][j] = 0.f;
                const __half* kaddr = &sK[(2 * g + hi1) * 8 + li7][c8];
#pragma unroll
                for (int ks = 0; ks < 4; ks++) {
                    uint32_t bb[4];
                    ldsm_x4(bb, kaddr + ks * 16);
                    mma16816(sacc[buf][0][0], aq[0][ks], bb);
                    mma16816(sacc[buf][0][1], aq[0][ks], bb + 2);
                    mma16816(sacc[buf][1][0], aq[1][ks], bb);
                    mma16816(sacc[buf][1][1], aq[1][ks], bb + 2);
                }
            }
            if (g > 0) {
                const int gg = g - 1;
                const int buf = gg & 1;
                uint32_t pp[2][4];
#pragma unroll
                for (int mi = 0; mi < 2; mi++) {
                    float p0 = ex2(sacc[buf][mi][0][0]);
                    float p1 = ex2(sacc[buf][mi][0][1]);
                    float p2 = ex2(sacc[buf][mi][0][2]);
                    float p3 = ex2(sacc[buf][mi][0][3]);
                    float p4 = ex2(sacc[buf][mi][1][0]);
                    float p5 = ex2(sacc[buf][mi][1][1]);
                    float p6 = ex2(sacc[buf][mi][1][2]);
                    float p7 = ex2(sacc[buf][mi][1][3]);
                    lsp[mi][0] += (p0 + p1) + (p4 + p5);
                    lsp[mi][1] += (p2 + p3) + (p6 + p7);
                    pp[mi][0] = h2_as_u32(__floats2half2_rn(p0, p1));
                    pp[mi][1] = h2_as_u32(__floats2half2_rn(p2, p3));
                    pp[mi][2] = h2_as_u32(__floats2half2_rn(p4, p5));
                    pp[mi][3] = h2_as_u32(__floats2half2_rn(p6, p7));
                }
#pragma unroll
                for (int p = 0; p < 4; p++) {
                    uint32_t bv[4];
                    ldsm_x4_t(bv, &sV[gg * 16 + li15][p * 16 + hi8]);
                    mma16816(oa[0][2 * p], pp[0], bv);
                    mma16816(oa[0][2 * p + 1], pp[0], bv + 2);
                    mma16816(oa[1][2 * p], pp[1], bv);
                    mma16816(oa[1][2 * p + 1], pp[1], bv + 2);
                }
            }
        }

        if (sc < 7) {
            cp_wait0();
            __syncthreads();
        }
    }

#pragma unroll
    for (int mi = 0; mi < 2; mi++) {
        float s0 = lsp[mi][0], s1 = lsp[mi][1];
        s0 += __shfl_xor_sync(0xffffffffu, s0, 1);
        s0 += __shfl_xor_sync(0xffffffffu, s0, 2);
        s1 += __shfl_xor_sync(0xffffffffu, s1, 1);
        s1 += __shfl_xor_sync(0xffffffffu, s1, 2);
        float inv0 = __fdividef(1.f, s0);
        float inv1 = __fdividef(1.f, s1);
        int r = l0 + w * 32 + mi * 16 + (lane >> 2);
        size_t base0 = ((size_t)b * L_ + r) * IN_ + h * 64 + (lane & 3) * 2;
        size_t base1 = base0 + (size_t)8 * IN_;
#pragma unroll
        for (int nd = 0; nd < 8; nd++) {
            *(__half2*)(g_o + base0 + nd * 8) =
                __floats2half2_rn(oa[mi][nd][0] * inv0, oa[mi][nd][1] * inv0);
            *(__half2*)(g_o + base1 + nd * 8) =
                __floats2half2_rn(oa[mi][nd][2] * inv1, oa[mi][nd][3] * inv1);
        }
    }
}

// ---------------- launch ----------------
extern "C" void kernel_launch(void* const* d_in, const int* in_sizes, int n_in,
                              void* d_out, int out_size) {
    const float* x   = (const float*)d_in[0];
    const float* ctx = (const float*)d_in[1];
    const int*   seq = (const int*)d_in[2];
    const float* Wq  = (const float*)d_in[3];
    const float* Wk  = (const float*)d_in[4];
    const float* Wv  = (const float*)d_in[5];
    const float* Wo  = (const float*)d_in[6];
    const float* bo  = (const float*)d_in[7];
    float* out = (float*)d_out;

    void *pWq, *pWkv, *pWo, *pQ, *pKV, *pO;
    cudaGetSymbolAddress(&pWq, g_Wq);
    cudaGetSymbolAddress(&pWkv, g_Wkv);
    cudaGetSymbolAddress(&pWo, g_Wo);
    cudaGetSymbolAddress(&pQ, g_q);
    cudaGetSymbolAddress(&pKV, g_kv);
    cudaGetSymbolAddress(&pO, g_o);

    const float kQScale = 0.125f * 1.44269504088896f;  // 1/sqrt(DH) * log2(e)

    // 1. convert all weights in one launch
    f2h_all<<<1024, 256>>>(Wq, Wk, Wv, Wo, (__half*)pWq, (__half*)pWkv, (__half*)pWo);

    // 2+3. KV projection AND Q projection fused into one launch (2304 CTAs)
    gemm_qkv<<<2304, 256>>>(ctx, (const __half*)pWkv, (__half*)pKV,
                            x, (const __half*)pWq, (__half*)pQ, seq, kQScale);

    // 4. fused attention (R8 exact)
    attn_kernel<<<dim3(L_ / 128, H_, B_), 128>>>(seq);

    // 5. output projection + bias + seq_len zero-gating
    gemm_mma<false, true, false, true, true>
        <<<dim3(DQ_ / 128, (B_ * L_) / 128), 256>>>(pO, (const __half*)pWo, out,
                                                    B_ * L_, DQ_, IN_, seq, bo, 1.0f);
}